// round 15
// baseline (speedup 1.0000x reference)
#include <cuda_runtime.h>
#include <cuda_fp16.h>
#include <cstdint>

#define BB   32
#define NN   1024
#define HH   1024
#define NHD  16
#define DD   64
#define BH   (BB*NHD)     // 512
#define MROWS (BB*NN)     // 32768

// -------- scratch (device globals) --------
__device__ __half g_qh[BH * NN * DD];        // q hi/lo fp16
__device__ __half g_ql[BH * NN * DD];
__device__ __half g_kh[BH * NN * DD];        // khat = k+pe hi/lo fp16
__device__ __half g_kl[BH * NN * DD];
__device__ __half g_vh[BH * NN * DD];        // v hi/lo fp16
__device__ __half g_vl[BH * NN * DD];
__device__ __half g_xh[3][MROWS * HH];       // fp16 inputs
__device__ __half g_wh[4][HH * HH];          // fp16 weights
__device__ __half g_ch[MROWS * HH];          // fp16 ctx

// ============================================================
// fp32 -> fp16 convert, multi-source (blockIdx.y selects src)
// ============================================================
struct alignas(16) H8 { __half2 a, b, c, d; };
struct CvtSrc { const float* s[4]; };

__global__ void cvt_multi(CvtSrc ps, __half* __restrict__ out, int n)
{
    const float* __restrict__ in = ps.s[blockIdx.y];
    __half* __restrict__ dst = out + (size_t)blockIdx.y * n;
    int idx = (blockIdx.x * blockDim.x + threadIdx.x) * 8;
    if (idx >= n) return;
    float4 a = *reinterpret_cast<const float4*>(in + idx);
    float4 b = *reinterpret_cast<const float4*>(in + idx + 4);
    H8 o;
    o.a = __floats2half2_rn(a.x, a.y);
    o.b = __floats2half2_rn(a.z, a.w);
    o.c = __floats2half2_rn(b.x, b.y);
    o.d = __floats2half2_rn(b.z, b.w);
    *reinterpret_cast<H8*>(dst + idx) = o;
}

// ============================================================
// mma.sync helpers
// ============================================================
__device__ __forceinline__ uint32_t smem_u32(const void* p) {
    return (uint32_t)__cvta_generic_to_shared(p);
}
__device__ __forceinline__ void cp16(uint32_t dst, const void* src) {
    asm volatile("cp.async.cg.shared.global [%0], [%1], 16;\n" :: "r"(dst), "l"(src));
}
__device__ __forceinline__ void cp_commit() {
    asm volatile("cp.async.commit_group;\n");
}
template<int N> __device__ __forceinline__ void cp_wait() {
    asm volatile("cp.async.wait_group %0;\n" :: "n"(N));
}
__device__ __forceinline__ void ldsm_x4(uint32_t* r, uint32_t addr) {
    asm volatile("ldmatrix.sync.aligned.m8n8.x4.shared.b16 {%0,%1,%2,%3}, [%4];\n"
                 : "=r"(r[0]), "=r"(r[1]), "=r"(r[2]), "=r"(r[3]) : "r"(addr));
}
__device__ __forceinline__ void ldsm_x4_t(uint32_t* r, uint32_t addr) {
    asm volatile("ldmatrix.sync.aligned.m8n8.x4.trans.shared.b16 {%0,%1,%2,%3}, [%4];\n"
                 : "=r"(r[0]), "=r"(r[1]), "=r"(r[2]), "=r"(r[3]) : "r"(addr));
}
__device__ __forceinline__ void mma16816(float* c, const uint32_t* a, const uint32_t* b) {
    asm volatile("mma.sync.aligned.m16n8k16.row.col.f32.f16.f16.f32 "
                 "{%0,%1,%2,%3}, {%4,%5,%6,%7}, {%8,%9}, {%0,%1,%2,%3};\n"
                 : "+f"(c[0]), "+f"(c[1]), "+f"(c[2]), "+f"(c[3])
                 : "r"(a[0]), "r"(a[1]), "r"(a[2]), "r"(a[3]),
                   "r"(b[0]), "r"(b[1]));
}
// packed hi/lo split of (c0,c1) -> two half2
__device__ __forceinline__ void split2(float c0, float c1, __half2& H, __half2& L) {
    H = __float22half2_rn(make_float2(c0, c1));
    float2 hf = __half22float2(H);
    L = __float22half2_rn(make_float2(c0 - hf.x, c1 - hf.y));
}

// ============================================================
// GEMM config (shared by qkv-batched and out kernels)
// ============================================================
#define BM 128
#define BN 256
#define BKH 128
#define LDSS 136
#define NITER (HH / BKH)                  // 8
#define STG_A (BM * LDSS * 2)             // 34816 B
#define STG_B (BN * LDSS * 2)             // 69632 B
#define STG   (STG_A + STG_B)             // 104448 B
#define GSMEM (2 * STG)                   // 208896 B

// ---- common mainloop (macro-free, via inline) ----
struct QKVArgs {
    const __half* A[3];
    const __half* W[3];
    __half* Ch[3];
    __half* Cl[3];
    const float* PE;
};

// ============================================================
// Batched q/k/v projection GEMM: grid.z selects tensor.
// z==1 adds PE before the hi/lo split (khat).
// CTA 128x256, 512 threads, warp 32x64, K-tile 128, 2 stages.
// smem-staged coalesced hi/lo epilogue.
// ============================================================
__global__ void __launch_bounds__(512, 1)
hgemm_qkv(QKVArgs args)
{
    extern __shared__ __align__(16) char dynsm[];
    const uint32_t dbase = smem_u32(dynsm);

    const int z = blockIdx.z;
    const __half* __restrict__ A = args.A[z];
    const __half* __restrict__ W = args.W[z];
    __half* __restrict__ Ch = args.Ch[z];
    __half* __restrict__ Cl = args.Cl[z];
    const bool use_pe = (z == 1);

    const int tid  = threadIdx.x;
    const int lane = tid & 31;
    const int wid  = tid >> 5;
    const int bm = blockIdx.y * BM;
    const int bn = blockIdx.x * BN;

    // loader: 384 rows x 16 chunks of 8 halfs; 12 cp16/thread
    const __half* gsrc[12];
    uint32_t      soff[12];
#pragma unroll
    for (int i = 0; i < 12; ++i) {
        const int chunk = tid + i * 512;
        const int row = chunk >> 4;
        const int c   = chunk & 15;
        if (row < BM) {
            gsrc[i] = A + (size_t)(bm + row) * HH + c * 8;
            soff[i] = (uint32_t)(row * LDSS + c * 8) * 2;
        } else {
            const int r2 = row - BM;
            gsrc[i] = W + (size_t)(bn + r2) * HH + c * 8;
            soff[i] = (uint32_t)STG_A + (uint32_t)(r2 * LDSS + c * 8) * 2;
        }
    }

    auto issue = [&](int it, int buf) {
        const uint32_t sb = dbase + (uint32_t)buf * STG;
        const size_t kofs = (size_t)it * BKH;
#pragma unroll
        for (int i = 0; i < 12; ++i)
            cp16(sb + soff[i], gsrc[i] + kofs);
        cp_commit();
    };

    const int wm = (wid & 3) * 32;
    const int wn = (wid >> 2) * 64;
    const int lr = lane & 7;
    const int lt = lane >> 3;
    const int arow_f = wm + (lt & 1) * 8 + lr;
    const int akg    = lt >> 1;
    const int brow_f = wn + (lt >> 1) * 8 + lr;
    const int bkg    = lt & 1;

    float acc[2][8][4];
#pragma unroll
    for (int i = 0; i < 2; i++)
#pragma unroll
        for (int j = 0; j < 8; j++)
#pragma unroll
            for (int r = 0; r < 4; r++) acc[i][j][r] = 0.f;

    issue(0, 0);

    for (int it = 0; it < NITER; ++it) {
        cp_wait<0>();
        __syncthreads();

        if (it + 1 < NITER) issue(it + 1, (it + 1) & 1);

        const uint32_t sb = dbase + (uint32_t)(it & 1) * STG;

#pragma unroll
        for (int s = 0; s < 8; ++s) {
            uint32_t af[2][4];
#pragma unroll
            for (int mi = 0; mi < 2; ++mi)
                ldsm_x4(af[mi], sb +
                    (uint32_t)(((arow_f + mi * 16) * LDSS + (s * 2 + akg) * 8) * 2));
            uint32_t bf[4][4];
#pragma unroll
            for (int p = 0; p < 4; ++p)
                ldsm_x4(bf[p], sb + STG_A +
                    (uint32_t)(((brow_f + p * 16) * LDSS + (s * 2 + bkg) * 8) * 2));
#pragma unroll
            for (int mi = 0; mi < 2; ++mi)
#pragma unroll
                for (int ni = 0; ni < 8; ++ni)
                    mma16816(acc[mi][ni], af[mi], &bf[ni >> 1][(ni & 1) * 2]);
        }
    }

    // ---- smem-staged hi/lo epilogue ----
    __syncthreads();   // all mainloop smem reads done; buffers reusable

    float* pes = reinterpret_cast<float*>(dynsm);
    if (use_pe) {
        const float* pesrc = args.PE + (size_t)(bm & 1023) * 64;
#pragma unroll
        for (int i = tid; i < 2048; i += 512) {
            const int r  = i >> 4;
            const int c4 = (i & 15) * 4;
            *reinterpret_cast<float4*>(&pes[r * 68 + c4]) =
                *reinterpret_cast<const float4*>(&pesrc[r * 64 + c4]);
        }
        __syncthreads();
    }

    // staging planes: 512 rows (nh_l*128 + m_local) x 72 halfs, at +34816
    __half* s_hi = reinterpret_cast<__half*>(dynsm + 34816);
    __half* s_lo = s_hi + 512 * 72;
    const int nh_l = wid >> 2;

#pragma unroll
    for (int mi = 0; mi < 2; ++mi) {
#pragma unroll
        for (int ni = 0; ni < 8; ++ni) {
            const int d = ni * 8 + (lane & 3) * 2;
#pragma unroll
            for (int h = 0; h < 2; ++h) {
                const int ml = wm + mi * 16 + (lane >> 2) + h * 8;
                float c0 = acc[mi][ni][h * 2 + 0];
                float c1 = acc[mi][ni][h * 2 + 1];
                if (use_pe) {
                    c0 += pes[ml * 68 + d];
                    c1 += pes[ml * 68 + d + 1];
                }
                __half2 H, L;
                split2(c0, c1, H, L);
                const int r = nh_l * 128 + ml;
                *reinterpret_cast<__half2*>(&s_hi[r * 72 + d]) = H;
                *reinterpret_cast<__half2*>(&s_lo[r * 72 + d]) = L;
            }
        }
    }
    __syncthreads();

    // coalesced writeback: 4096 chunks of 16B per plane
    const int nh_base = bn >> 6;
#pragma unroll
    for (int i = 0; i < 8; ++i) {
        const int c = tid + i * 512;
        const int r = c >> 3, seg = c & 7;
        const int ml = r & 127, nhl2 = r >> 7;
        const int m = bm + ml;
        const int bI = m >> 10, n = m & 1023;
        const size_t dst = ((size_t)(bI * NHD + nh_base + nhl2) * NN + n) * DD + seg * 8;
        *reinterpret_cast<uint4*>(&Ch[dst]) =
            *reinterpret_cast<uint4*>(&s_hi[r * 72 + seg * 8]);
        *reinterpret_cast<uint4*>(&Cl[dst]) =
            *reinterpret_cast<uint4*>(&s_lo[r * 72 + seg * 8]);
    }
}

// ============================================================
// Output projection GEMM (fp32 row-major)
// ============================================================
__global__ void __launch_bounds__(512, 1)
hgemm_out(const __half* __restrict__ A, const __half* __restrict__ W,
          float* __restrict__ C)
{
    extern __shared__ __align__(16) char dynsm[];
    const uint32_t dbase = smem_u32(dynsm);

    const int tid  = threadIdx.x;
    const int lane = tid & 31;
    const int wid  = tid >> 5;
    const int bm = blockIdx.y * BM;
    const int bn = blockIdx.x * BN;

    const __half* gsrc[12];
    uint32_t      soff[12];
#pragma unroll
    for (int i = 0; i < 12; ++i) {
        const int chunk = tid + i * 512;
        const int row = chunk >> 4;
        const int c   = chunk & 15;
        if (row < BM) {
            gsrc[i] = A + (size_t)(bm + row) * HH + c * 8;
            soff[i] = (uint32_t)(row * LDSS + c * 8) * 2;
        } else {
            const int r2 = row - BM;
            gsrc[i] = W + (size_t)(bn + r2) * HH + c * 8;
            soff[i] = (uint32_t)STG_A + (uint32_t)(r2 * LDSS + c * 8) * 2;
        }
    }

    auto issue = [&](int it, int buf) {
        const uint32_t sb = dbase + (uint32_t)buf * STG;
        const size_t kofs = (size_t)it * BKH;
#pragma unroll
        for (int i = 0; i < 12; ++i)
            cp16(sb + soff[i], gsrc[i] + kofs);
        cp_commit();
    };

    const int wm = (wid & 3) * 32;
    const int wn = (wid >> 2) * 64;
    const int lr = lane & 7;
    const int lt = lane >> 3;
    const int arow_f = wm + (lt & 1) * 8 + lr;
    const int akg    = lt >> 1;
    const int brow_f = wn + (lt >> 1) * 8 + lr;
    const int bkg    = lt & 1;

    float acc[2][8][4];
#pragma unroll
    for (int i = 0; i < 2; i++)
#pragma unroll
        for (int j = 0; j < 8; j++)
#pragma unroll
            for (int r = 0; r < 4; r++) acc[i][j][r] = 0.f;

    issue(0, 0);

    for (int it = 0; it < NITER; ++it) {
        cp_wait<0>();
        __syncthreads();
        if (it + 1 < NITER) issue(it + 1, (it + 1) & 1);
        const uint32_t sb = dbase + (uint32_t)(it & 1) * STG;

#pragma unroll
        for (int s = 0; s < 8; ++s) {
            uint32_t af[2][4];
#pragma unroll
            for (int mi = 0; mi < 2; ++mi)
                ldsm_x4(af[mi], sb +
                    (uint32_t)(((arow_f + mi * 16) * LDSS + (s * 2 + akg) * 8) * 2));
            uint32_t bf[4][4];
#pragma unroll
            for (int p = 0; p < 4; ++p)
                ldsm_x4(bf[p], sb + STG_A +
                    (uint32_t)(((brow_f + p * 16) * LDSS + (s * 2 + bkg) * 8) * 2));
#pragma unroll
            for (int mi = 0; mi < 2; ++mi)
#pragma unroll
                for (int ni = 0; ni < 8; ++ni)
                    mma16816(acc[mi][ni], af[mi], &bf[ni >> 1][(ni & 1) * 2]);
        }
    }

#pragma unroll
    for (int mi = 0; mi < 2; ++mi) {
#pragma unroll
        for (int ni = 0; ni < 8; ++ni) {
            const int m0 = bm + wm + mi * 16 + (lane >> 2);
            const int n0 = bn + wn + ni * 8 + (lane & 3) * 2;
#pragma unroll
            for (int h = 0; h < 2; ++h) {
                const int m = m0 + h * 8;
                *reinterpret_cast<float2*>(&C[(size_t)m * HH + n0]) =
                    make_float2(acc[mi][ni][h * 2 + 0], acc[mi][ni][h * 2 + 1]);
            }
        }
    }
}

// ============================================================
// attn_fused: per b — scores+softmax+AV, fragment-shared 3-pass hi/lo MMA.
// Per k-step: 6 unique ldsm (aH,aL,bH0,bH1,bL0,bL1) feed 12 MMAs.
// 256 threads; dynamic smem 92160 B; occ 2.
// ============================================================
#define SLD 72                         // smem tile stride, halfs (144B rows)
#define TILE (64 * SLD * 2)            // 9216 B per tile
#define S1STG (4 * TILE)               // 36864 B per phase-1 stage
#define ATT_OFF (2 * S1STG)            // 73728: attn hi tile
#define ATSM (ATT_OFF + 2 * TILE)      // 92160 total

__global__ void __launch_bounds__(256, 2)
attn_fused(const __half* __restrict__ qh, const __half* __restrict__ ql,
           const __half* __restrict__ kh, const __half* __restrict__ kl,
           const __half* __restrict__ vh, const __half* __restrict__ vl,
           __half* __restrict__ ch)
{
    const int b = blockIdx.x;
    extern __shared__ __align__(16) char dynsm[];
    const uint32_t dbase = smem_u32(dynsm);

    const int tid = threadIdx.x;
    const int lane = tid & 31;
    const int wid = tid >> 5;
    const size_t bb64 = (size_t)b * (NN * DD);
    const int lr = lane & 7;
    const int lt = lane >> 3;

    // ================= phase 1: scores =================
    {
        const __half* bases[4] = { qh + bb64, ql + bb64, kh + bb64, kl + bb64 };
        const __half* lsrc[8];
        uint32_t      ldst[8];
#pragma unroll
        for (int j = 0; j < 8; ++j) {
            const int c2 = tid + j * 256;
            const int t  = c2 >> 9;
            const int r  = (c2 >> 3) & 63;
            const int cc = c2 & 7;
            lsrc[j] = bases[t] + r * 64 + cc * 8;
            ldst[j] = (uint32_t)(t * TILE) + (uint32_t)(r * SLD + cc * 8) * 2;
        }

        auto issue1 = [&](int c, int buf) {
            const uint32_t sb = dbase + (uint32_t)buf * S1STG;
            const size_t ofs = (size_t)c * 4096;
#pragma unroll
            for (int j = 0; j < 8; ++j)
                cp16(sb + ldst[j], lsrc[j] + ofs);
            cp_commit();
        };

        const int wm = (wid & 3) * 16;      // d strip
        const int wn = (wid >> 2) * 32;     // e strip
        const int a_moff = (lt & 1) * 8;
        const int a_koff = (lt >> 1) * 8;
        const int b_koff = (lt & 1) * 8;
        const int b_noff = (lt >> 1) * 8;

        float acc[4][4];
#pragma unroll
        for (int i = 0; i < 4; i++)
#pragma unroll
            for (int j = 0; j < 4; j++) acc[i][j] = 0.f;

        issue1(0, 0);

        for (int c = 0; c < 16; ++c) {
            cp_wait<0>();
            __syncthreads();
            if (c + 1 < 16) issue1(c + 1, (c + 1) & 1);

            const uint32_t sb = dbase + (uint32_t)(c & 1) * S1STG;
            const uint32_t qh_t = sb,          ql_t = sb + TILE;
            const uint32_t kh_t = sb + 2*TILE, kl_t = sb + 3*TILE;
#pragma unroll
            for (int s = 0; s < 4; ++s) {
                const uint32_t a_off =
                    (uint32_t)(((s * 16 + a_koff + lr) * SLD + wm + a_moff) * 2);
                const uint32_t b_off0 =
                    (uint32_t)(((s * 16 + b_koff + lr) * SLD + wn + b_noff) * 2);
                const uint32_t b_off1 =
                    (uint32_t)(((s * 16 + b_koff + lr) * SLD + wn + 16 + b_noff) * 2);
                uint32_t aH[4], aL[4], bHf[2][4], bLf[2][4];
                ldsm_x4_t(aH, qh_t + a_off);
                ldsm_x4_t(aL, ql_t + a_off);
                ldsm_x4_t(bHf[0], kh_t + b_off0);
                ldsm_x4_t(bHf[1], kh_t + b_off1);
                ldsm_x4_t(bLf[0], kl_t + b_off0);
                ldsm_x4_t(bLf[1], kl_t + b_off1);
#pragma unroll
                for (int ni = 0; ni < 4; ++ni)
                    mma16816(acc[ni], aH, &bHf[ni >> 1][(ni & 1) * 2]);
#pragma unroll
                for (int ni = 0; ni < 4; ++ni)
                    mma16816(acc[ni], aH, &bLf[ni >> 1][(ni & 1) * 2]);
#pragma unroll
                for (int ni = 0; ni < 4; ++ni)
                    mma16816(acc[ni], aL, &bHf[ni >> 1][(ni & 1) * 2]);
            }
        }

        __syncthreads();
        float (*sc)[68] = reinterpret_cast<float(*)[68]>(dynsm);
#pragma unroll
        for (int ni = 0; ni < 4; ++ni) {
            const int e = wn + ni * 8 + (lane & 3) * 2;
            const int r = wm + (lane >> 2);
            sc[r][e]         = acc[ni][0];
            sc[r][e + 1]     = acc[ni][1];
            sc[r + 8][e]     = acc[ni][2];
            sc[r + 8][e + 1] = acc[ni][3];
        }
        __syncthreads();

        __half* ah_s = reinterpret_cast<__half*>(dynsm + ATT_OFF);
        __half* al_s = ah_s + 64 * SLD;
        for (int rr = 0; rr < 8; ++rr) {
            const int row = wid * 8 + rr;
            float v0 = sc[row][lane]      * 0.125f;
            float v1 = sc[row][lane + 32] * 0.125f;
            float m = fmaxf(v0, v1);
#pragma unroll
            for (int off = 16; off > 0; off >>= 1)
                m = fmaxf(m, __shfl_xor_sync(0xFFFFFFFFu, m, off));
            float e0 = __expf(v0 - m);
            float e1 = __expf(v1 - m);
            float sum = e0 + e1;
#pragma unroll
            for (int off = 16; off > 0; off >>= 1)
                sum += __shfl_xor_sync(0xFFFFFFFFu, sum, off);
            const float inv = 1.0f / sum;
            const float p0 = e0 * inv, p1 = e1 * inv;
            __half h0 = __float2half_rn(p0);
            __half h1 = __float2half_rn(p1);
            ah_s[row * SLD + lane]      = h0;
            ah_s[row * SLD + lane + 32] = h1;
            al_s[row * SLD + lane]      = __float2half_rn(p0 - __half2float(h0));
            al_s[row * SLD + lane + 32] = __float2half_rn(p1 - __half2float(h1));
        }
        __syncthreads();
    }

    // ================= phase 2: AV =================
    {
        const uint32_t ah_a = dbase + ATT_OFF;
        const uint32_t al_a = ah_a + TILE;

        const __half* vsrc[4];
        uint32_t      vdst[4];
#pragma unroll
        for (int j = 0; j < 4; ++j) {
            const int c2 = tid + j * 256;
            const int t  = c2 >> 9;
            const int r  = (c2 >> 3) & 63;
            const int cc = c2 & 7;
            vsrc[j] = (t ? vl : vh) + bb64 + r * 64 + cc * 8;
            vdst[j] = (uint32_t)(t * TILE) + (uint32_t)(r * SLD + cc * 8) * 2;
        }

        auto issue2 = [&](int c, int buf) {
            const uint32_t sb = dbase + (uint32_t)buf * (2 * TILE);
            const size_t ofs = (size_t)c * 4096;
#pragma unroll
            for (int j = 0; j < 4; ++j)
                cp16(sb + vdst[j], vsrc[j] + ofs);
            cp_commit();
        };

        const int wm = (wid & 3) * 16;     // n strip
        const int wn = (wid >> 2) * 32;    // d strip
        const int arow = wm + (lt & 1) * 8 + lr;
        const int akg  = lt >> 1;
        const int brow = wn + (lt >> 1) * 8 + lr;
        const int bkg  = lt & 1;
        const int bbn = b >> 4;
        const int nh  = b & 15;

        issue2(0, 0);

        for (int c = 0; c < 16; ++c) {
            cp_wait<0>();
            __syncthreads();
            if (c + 1 < 16) issue2(c + 1, (c + 1) & 1);

            const uint32_t sb = dbase + (uint32_t)(c & 1) * (2 * TILE);
            const uint32_t vh_t = sb, vl_t = sb + TILE;

            float acc[4][4];
#pragma unroll
            for (int i = 0; i < 4; i++)
#pragma unroll
                for (int j = 0; j < 4; j++) acc[i][j] = 0.f;

#pragma unroll
            for (int s = 0; s < 4; ++s) {
                const uint32_t a_off =
                    (uint32_t)((arow * SLD + (s * 2 + akg) * 8) * 2);
                const uint32_t b_off0 =
                    (uint32_t)((brow * SLD + (s * 2 + bkg) * 8) * 2);
                const uint32_t b_off1 =
                    (uint32_t)(((brow + 16) * SLD + (s * 2 + bkg) * 8) * 2);
                uint32_t aH[4], aL[4], bHf[2][4], bLf[2][4];
                ldsm_x4(aH, vh_t + a_off);
                ldsm_x4(aL, vl_t + a_off);
                ldsm_x4(bHf[0], ah_a + b_off0);
                ldsm_x4(bHf[1], ah_a + b_off1);
                ldsm_x4(bLf[0], al_a + b_off0);
                ldsm_x4(bLf[1], al_a + b_off1);
#pragma unroll
                for (int ni = 0; ni < 4; ++ni)
                    mma16816(acc[ni], aH, &bHf[ni >> 1][(ni & 1) * 2]);
#pragma unroll
                for (int ni = 0; ni < 4; ++ni)
                    mma16816(acc[ni], aH, &bLf[ni >> 1][(ni & 1) * 2]);
#pragma unroll
                for (int ni = 0; ni < 4; ++ni)
                    mma16816(acc[ni], aL, &bHf[ni >> 1][(ni & 1) * 2]);
            }

            const int n0 = c * 64;
#pragma unroll
            for (int ni = 0; ni < 4; ++ni) {
                const int dcol = wn + ni * 8 + (lane & 3) * 2;
                const int nrow = n0 + wm + (lane >> 2);
#pragma unroll
                for (int h = 0; h < 2; ++h) {
                    const int n = nrow + h * 8;
                    const size_t idx = ((size_t)bbn * NN + n) * HH + nh * 64 + dcol;
                    *reinterpret_cast<__half2*>(&ch[idx]) =
                        __float22half2_rn(make_float2(acc[ni][h * 2],
                                                      acc[ni][h * 2 + 1]));
                }
            }
        }
    }
}

// ============================================================
// launch  (my call #4 = attn_fused -> profiled launch)
// ============================================================
extern "C" void kernel_launch(void* const* d_in, const int* in_sizes, int n_in,
                              void* d_out, int out_size)
{
    const float* query  = (const float*)d_in[0];
    const float* key    = (const float*)d_in[1];
    const float* value  = (const float*)d_in[2];
    const float* key_pe = (const float*)d_in[3];
    const float* Wq     = (const float*)d_in[4];
    const float* Wk     = (const float*)d_in[5];
    const float* Wv     = (const float*)d_in[6];
    const float* Wo     = (const float*)d_in[7];
    float* out = (float*)d_out;

    __half *qh, *ql, *kh, *kl, *vh, *vl, *xh, *wh, *ch;
    cudaGetSymbolAddress((void**)&qh, g_qh);
    cudaGetSymbolAddress((void**)&ql, g_ql);
    cudaGetSymbolAddress((void**)&kh, g_kh);
    cudaGetSymbolAddress((void**)&kl, g_kl);
    cudaGetSymbolAddress((void**)&vh, g_vh);
    cudaGetSymbolAddress((void**)&vl, g_vl);
    cudaGetSymbolAddress((void**)&xh, g_xh);
    cudaGetSymbolAddress((void**)&wh, g_wh);
    cudaGetSymbolAddress((void**)&ch, g_ch);

    static bool attr_done = false;
    if (!attr_done) {
        cudaFuncSetAttribute(hgemm_qkv, cudaFuncAttributeMaxDynamicSharedMemorySize, GSMEM);
        cudaFuncSetAttribute(hgemm_out, cudaFuncAttributeMaxDynamicSharedMemorySize, GSMEM);
        cudaFuncSetAttribute(attn_fused, cudaFuncAttributeMaxDynamicSharedMemorySize, ATSM);
        attr_done = true;
    }

    const int nX = MROWS * HH;
    const int nW = HH * HH;

    CvtSrc xs; xs.s[0] = query; xs.s[1] = key; xs.s[2] = value; xs.s[3] = nullptr;
    CvtSrc ws; ws.s[0] = Wq; ws.s[1] = Wk; ws.s[2] = Wv; ws.s[3] = Wo;

    QKVArgs qa;
    qa.A[0] = xh + 0 * (size_t)nX;  qa.W[0] = wh + 0 * (size_t)nW;
    qa.A[1] = xh + 1 * (size_t)nX;  qa.W[1] = wh + 1 * (size_t)nW;
    qa.A[2] = xh + 2 * (size_t)nX;  qa.W[2] = wh + 2 * (size_t)nW;
    qa.Ch[0] = qh; qa.Cl[0] = ql;
    qa.Ch[1] = kh; qa.Cl[1] = kl;
    qa.Ch[2] = vh; qa.Cl[2] = vl;
    qa.PE = key_pe;

    cvt_multi<<<dim3(nX / 2048, 3), 256>>>(xs, xh, nX);                 // 1
    cvt_multi<<<dim3(nW / 2048, 4), 256>>>(ws, wh, nW);                 // 2

    hgemm_qkv<<<dim3(HH / BN, MROWS / BM, 3), 512, GSMEM>>>(qa);        // 3

    attn_fused<<<BH, 256, ATSM>>>(qh, ql, kh, kl, vh, vl, ch);          // 4 <- profiled

    hgemm_out<<<dim3(HH / BN, MROWS / BM), 512, GSMEM>>>(
        ch, wh + 3 * (size_t)nW, out);                                  // 5
}

// round 16
// speedup vs baseline: 1.0138x; 1.0138x over previous
#include <cuda_runtime.h>
#include <cuda_fp16.h>
#include <cstdint>

#define BB   32
#define NN   1024
#define HH   1024
#define NHD  16
#define DD   64
#define BH   (BB*NHD)     // 512
#define MROWS (BB*NN)     // 32768

// -------- scratch (device globals) --------
__device__ __half g_qh[BH * NN * DD];        // q hi/lo fp16
__device__ __half g_ql[BH * NN * DD];
__device__ __half g_kh[BH * NN * DD];        // khat = k+pe hi/lo fp16
__device__ __half g_kl[BH * NN * DD];
__device__ __half g_vh[BH * NN * DD];        // v hi/lo fp16
__device__ __half g_vl[BH * NN * DD];
__device__ __half g_xh[3][MROWS * HH];       // fp16 inputs
__device__ __half g_wh[4][HH * HH];          // fp16 weights
__device__ __half g_ch[MROWS * HH];          // fp16 ctx

// ============================================================
// fp32 -> fp16 convert, multi-source
// ============================================================
struct alignas(16) H8 { __half2 a, b, c, d; };
struct CvtSrc { const float* s[4]; };

__global__ void cvt_multi(CvtSrc ps, __half* __restrict__ out, int n)
{
    const float* __restrict__ in = ps.s[blockIdx.y];
    __half* __restrict__ dst = out + (size_t)blockIdx.y * n;
    int idx = (blockIdx.x * blockDim.x + threadIdx.x) * 8;
    if (idx >= n) return;
    float4 a = *reinterpret_cast<const float4*>(in + idx);
    float4 b = *reinterpret_cast<const float4*>(in + idx + 4);
    H8 o;
    o.a = __floats2half2_rn(a.x, a.y);
    o.b = __floats2half2_rn(a.z, a.w);
    o.c = __floats2half2_rn(b.x, b.y);
    o.d = __floats2half2_rn(b.z, b.w);
    *reinterpret_cast<H8*>(dst + idx) = o;
}

// ============================================================
// mma.sync helpers
// ============================================================
__device__ __forceinline__ uint32_t smem_u32(const void* p) {
    return (uint32_t)__cvta_generic_to_shared(p);
}
__device__ __forceinline__ void cp16(uint32_t dst, const void* src) {
    asm volatile("cp.async.cg.shared.global [%0], [%1], 16;\n" :: "r"(dst), "l"(src));
}
__device__ __forceinline__ void cp_commit() {
    asm volatile("cp.async.commit_group;\n");
}
template<int N> __device__ __forceinline__ void cp_wait() {
    asm volatile("cp.async.wait_group %0;\n" :: "n"(N));
}
__device__ __forceinline__ void ldsm_x4(uint32_t* r, uint32_t addr) {
    asm volatile("ldmatrix.sync.aligned.m8n8.x4.shared.b16 {%0,%1,%2,%3}, [%4];\n"
                 : "=r"(r[0]), "=r"(r[1]), "=r"(r[2]), "=r"(r[3]) : "r"(addr));
}
__device__ __forceinline__ void ldsm_x4_t(uint32_t* r, uint32_t addr) {
    asm volatile("ldmatrix.sync.aligned.m8n8.x4.trans.shared.b16 {%0,%1,%2,%3}, [%4];\n"
                 : "=r"(r[0]), "=r"(r[1]), "=r"(r[2]), "=r"(r[3]) : "r"(addr));
}
__device__ __forceinline__ void mma16816(float* c, const uint32_t* a, const uint32_t* b) {
    asm volatile("mma.sync.aligned.m16n8k16.row.col.f32.f16.f16.f32 "
                 "{%0,%1,%2,%3}, {%4,%5,%6,%7}, {%8,%9}, {%0,%1,%2,%3};\n"
                 : "+f"(c[0]), "+f"(c[1]), "+f"(c[2]), "+f"(c[3])
                 : "r"(a[0]), "r"(a[1]), "r"(a[2]), "r"(a[3]),
                   "r"(b[0]), "r"(b[1]));
}
__device__ __forceinline__ void split2(float c0, float c1, __half2& H, __half2& L) {
    H = __float22half2_rn(make_float2(c0, c1));
    float2 hf = __half22float2(H);
    L = __float22half2_rn(make_float2(c0 - hf.x, c1 - hf.y));
}

// ============================================================
// HMMA GEMM NT: C[m,h] = sum_k A[m,k]*W[h,k]  (fp16 in, fp32 acc)
// CTA 128x256, 512 threads, warp 32x64, K-tile 128, 2 stages.
// MODE 0: fp32 row-major   MODE 2: hi/lo head-split (staged)
// MODE 3: MODE2 + pe
// ============================================================
#define BM 128
#define BN 256
#define BKH 128
#define LDSS 136
#define NITER (HH / BKH)                  // 8
#define STG_A (BM * LDSS * 2)             // 34816 B
#define STG_B (BN * LDSS * 2)             // 69632 B
#define STG   (STG_A + STG_B)             // 104448 B
#define GSMEM (2 * STG)                   // 208896 B

template<int MODE>
__global__ void __launch_bounds__(512, 1)
hgemm_nt(const __half* __restrict__ A, const __half* __restrict__ W,
         float* __restrict__ C, __half* __restrict__ Ch, __half* __restrict__ Cl,
         const float* __restrict__ PE)
{
    extern __shared__ __align__(16) char dynsm[];
    const uint32_t dbase = smem_u32(dynsm);

    const int tid  = threadIdx.x;
    const int lane = tid & 31;
    const int wid  = tid >> 5;
    const int bm = blockIdx.y * BM;
    const int bn = blockIdx.x * BN;

    const __half* gsrc[12];
    uint32_t      soff[12];
#pragma unroll
    for (int i = 0; i < 12; ++i) {
        const int chunk = tid + i * 512;
        const int row = chunk >> 4;
        const int c   = chunk & 15;
        if (row < BM) {
            gsrc[i] = A + (size_t)(bm + row) * HH + c * 8;
            soff[i] = (uint32_t)(row * LDSS + c * 8) * 2;
        } else {
            const int r2 = row - BM;
            gsrc[i] = W + (size_t)(bn + r2) * HH + c * 8;
            soff[i] = (uint32_t)STG_A + (uint32_t)(r2 * LDSS + c * 8) * 2;
        }
    }

    auto issue = [&](int it, int buf) {
        const uint32_t sb = dbase + (uint32_t)buf * STG;
        const size_t kofs = (size_t)it * BKH;
#pragma unroll
        for (int i = 0; i < 12; ++i)
            cp16(sb + soff[i], gsrc[i] + kofs);
        cp_commit();
    };

    const int wm = (wid & 3) * 32;
    const int wn = (wid >> 2) * 64;
    const int lr = lane & 7;
    const int lt = lane >> 3;
    const int arow_f = wm + (lt & 1) * 8 + lr;
    const int akg    = lt >> 1;
    const int brow_f = wn + (lt >> 1) * 8 + lr;
    const int bkg    = lt & 1;

    float acc[2][8][4];
#pragma unroll
    for (int i = 0; i < 2; i++)
#pragma unroll
        for (int j = 0; j < 8; j++)
#pragma unroll
            for (int r = 0; r < 4; r++) acc[i][j][r] = 0.f;

    issue(0, 0);

    for (int it = 0; it < NITER; ++it) {
        cp_wait<0>();
        __syncthreads();
        if (it + 1 < NITER) issue(it + 1, (it + 1) & 1);
        const uint32_t sb = dbase + (uint32_t)(it & 1) * STG;

#pragma unroll
        for (int s = 0; s < 8; ++s) {
            uint32_t af[2][4];
#pragma unroll
            for (int mi = 0; mi < 2; ++mi)
                ldsm_x4(af[mi], sb +
                    (uint32_t)(((arow_f + mi * 16) * LDSS + (s * 2 + akg) * 8) * 2));
            uint32_t bf[4][4];
#pragma unroll
            for (int p = 0; p < 4; ++p)
                ldsm_x4(bf[p], sb + STG_A +
                    (uint32_t)(((brow_f + p * 16) * LDSS + (s * 2 + bkg) * 8) * 2));
#pragma unroll
            for (int mi = 0; mi < 2; ++mi)
#pragma unroll
                for (int ni = 0; ni < 8; ++ni)
                    mma16816(acc[mi][ni], af[mi], &bf[ni >> 1][(ni & 1) * 2]);
        }
    }

    if (MODE == 0) {
#pragma unroll
        for (int mi = 0; mi < 2; ++mi) {
#pragma unroll
            for (int ni = 0; ni < 8; ++ni) {
                const int m0 = bm + wm + mi * 16 + (lane >> 2);
                const int n0 = bn + wn + ni * 8 + (lane & 3) * 2;
#pragma unroll
                for (int h = 0; h < 2; ++h) {
                    const int m = m0 + h * 8;
                    *reinterpret_cast<float2*>(&C[(size_t)m * HH + n0]) =
                        make_float2(acc[mi][ni][h * 2 + 0], acc[mi][ni][h * 2 + 1]);
                }
            }
        }
    } else {
        __syncthreads();

        float* pes = reinterpret_cast<float*>(dynsm);
        if (MODE == 3) {
            const float* pesrc = PE + (size_t)(bm & 1023) * 64;
#pragma unroll
            for (int i = tid; i < 2048; i += 512) {
                const int r  = i >> 4;
                const int c4 = (i & 15) * 4;
                *reinterpret_cast<float4*>(&pes[r * 68 + c4]) =
                    *reinterpret_cast<const float4*>(&pesrc[r * 64 + c4]);
            }
            __syncthreads();
        }

        __half* s_hi = reinterpret_cast<__half*>(dynsm + (MODE == 3 ? 34816 : 0));
        __half* s_lo = s_hi + 512 * 72;
        const int nh_l = wid >> 2;

#pragma unroll
        for (int mi = 0; mi < 2; ++mi) {
#pragma unroll
            for (int ni = 0; ni < 8; ++ni) {
                const int d = ni * 8 + (lane & 3) * 2;
#pragma unroll
                for (int h = 0; h < 2; ++h) {
                    const int ml = wm + mi * 16 + (lane >> 2) + h * 8;
                    float c0 = acc[mi][ni][h * 2 + 0];
                    float c1 = acc[mi][ni][h * 2 + 1];
                    if (MODE == 3) {
                        c0 += pes[ml * 68 + d];
                        c1 += pes[ml * 68 + d + 1];
                    }
                    __half2 H, L;
                    split2(c0, c1, H, L);
                    const int r = nh_l * 128 + ml;
                    *reinterpret_cast<__half2*>(&s_hi[r * 72 + d]) = H;
                    *reinterpret_cast<__half2*>(&s_lo[r * 72 + d]) = L;
                }
            }
        }
        __syncthreads();

        const int nh_base = bn >> 6;
#pragma unroll
        for (int i = 0; i < 8; ++i) {
            const int c = tid + i * 512;
            const int r = c >> 3, seg = c & 7;
            const int ml = r & 127, nhl2 = r >> 7;
            const int m = bm + ml;
            const int bI = m >> 10, n = m & 1023;
            const size_t dst = ((size_t)(bI * NHD + nh_base + nhl2) * NN + n) * DD + seg * 8;
            *reinterpret_cast<uint4*>(&Ch[dst]) =
                *reinterpret_cast<uint4*>(&s_hi[r * 72 + seg * 8]);
            *reinterpret_cast<uint4*>(&Cl[dst]) =
                *reinterpret_cast<uint4*>(&s_lo[r * 72 + seg * 8]);
        }
    }
}

// ============================================================
// attn_fused: per b — scores+softmax+AV, hi/lo 3-term MMA.
// Phase 1 uses 32-row n-chunks (small smem) -> 3 CTAs/SM.
// smem: 2 x 18432 stages | attn tiles 2 x 9216 at +36864 = 55296 B.
// ============================================================
#define SLD 72                           // tile stride, halfs
#define T32 (32 * SLD * 2)               // 4608 B (32-row tile)
#define P1STG (4 * T32)                  // 18432 B per phase-1 stage
#define TILE64 (64 * SLD * 2)            // 9216 B (64-row tile)
#define ATT_OFF (2 * P1STG)              // 36864
#define ATSM (ATT_OFF + 2 * TILE64)      // 55296 B

__global__ void __launch_bounds__(256, 3)
attn_fused(const __half* __restrict__ qh, const __half* __restrict__ ql,
           const __half* __restrict__ kh, const __half* __restrict__ kl,
           const __half* __restrict__ vh, const __half* __restrict__ vl,
           __half* __restrict__ ch)
{
    const int b = blockIdx.x;
    extern __shared__ __align__(16) char dynsm[];
    const uint32_t dbase = smem_u32(dynsm);

    const int tid = threadIdx.x;
    const int lane = tid & 31;
    const int wid = tid >> 5;
    const size_t bb64 = (size_t)b * (NN * DD);
    const int lr = lane & 7;
    const int lt = lane >> 3;

    // ================= phase 1: scores (32-row chunks x32) =================
    {
        const __half* bases[4] = { qh + bb64, ql + bb64, kh + bb64, kl + bb64 };
        const __half* lsrc[4];
        uint32_t      ldst[4];
#pragma unroll
        for (int j = 0; j < 4; ++j) {
            const int c2 = tid + j * 256;          // 0..1023
            const int t  = c2 >> 8;                // tensor 0..3
            const int r  = (c2 >> 3) & 31;         // row within 32
            const int cc = c2 & 7;
            lsrc[j] = bases[t] + r * 64 + cc * 8;
            ldst[j] = (uint32_t)(t * T32) + (uint32_t)(r * SLD + cc * 8) * 2;
        }

        auto issue1 = [&](int c, int buf) {
            const uint32_t sb = dbase + (uint32_t)buf * P1STG;
            const size_t ofs = (size_t)c * 2048;   // 32 rows x 64 halfs
#pragma unroll
            for (int j = 0; j < 4; ++j)
                cp16(sb + ldst[j], lsrc[j] + ofs);
            cp_commit();
        };

        const int wm = (wid & 3) * 16;      // d strip
        const int wn = (wid >> 2) * 32;     // e strip
        const int a_moff = (lt & 1) * 8;
        const int a_koff = (lt >> 1) * 8;
        const int b_koff = (lt & 1) * 8;
        const int b_noff = (lt >> 1) * 8;

        float acc[4][4];
#pragma unroll
        for (int i = 0; i < 4; i++)
#pragma unroll
            for (int j = 0; j < 4; j++) acc[i][j] = 0.f;

        issue1(0, 0);

        for (int c = 0; c < 32; ++c) {
            cp_wait<0>();
            __syncthreads();
            if (c + 1 < 32) issue1(c + 1, (c + 1) & 1);

            const uint32_t sb = dbase + (uint32_t)(c & 1) * P1STG;
            const uint32_t qh_t = sb,         ql_t = sb + T32;
            const uint32_t kh_t = sb + 2*T32, kl_t = sb + 3*T32;
#pragma unroll
            for (int s = 0; s < 2; ++s) {
                const uint32_t a_off =
                    (uint32_t)(((s * 16 + a_koff + lr) * SLD + wm + a_moff) * 2);
                const uint32_t b_off0 =
                    (uint32_t)(((s * 16 + b_koff + lr) * SLD + wn + b_noff) * 2);
                const uint32_t b_off1 =
                    (uint32_t)(((s * 16 + b_koff + lr) * SLD + wn + 16 + b_noff) * 2);
                uint32_t aH[4], aL[4], bHf[2][4], bLf[2][4];
                ldsm_x4_t(aH, qh_t + a_off);
                ldsm_x4_t(aL, ql_t + a_off);
                ldsm_x4_t(bHf[0], kh_t + b_off0);
                ldsm_x4_t(bHf[1], kh_t + b_off1);
                ldsm_x4_t(bLf[0], kl_t + b_off0);
                ldsm_x4_t(bLf[1], kl_t + b_off1);
#pragma unroll
                for (int ni = 0; ni < 4; ++ni)
                    mma16816(acc[ni], aH, &bHf[ni >> 1][(ni & 1) * 2]);
#pragma unroll
                for (int ni = 0; ni < 4; ++ni)
                    mma16816(acc[ni], aH, &bLf[ni >> 1][(ni & 1) * 2]);
#pragma unroll
                for (int ni = 0; ni < 4; ++ni)
                    mma16816(acc[ni], aL, &bHf[ni >> 1][(ni & 1) * 2]);
            }
        }

        __syncthreads();
        float (*sc)[68] = reinterpret_cast<float(*)[68]>(dynsm);
#pragma unroll
        for (int ni = 0; ni < 4; ++ni) {
            const int e = wn + ni * 8 + (lane & 3) * 2;
            const int r = wm + (lane >> 2);
            sc[r][e]         = acc[ni][0];
            sc[r][e + 1]     = acc[ni][1];
            sc[r + 8][e]     = acc[ni][2];
            sc[r + 8][e + 1] = acc[ni][3];
        }
        __syncthreads();

        __half* ah_s = reinterpret_cast<__half*>(dynsm + ATT_OFF);
        __half* al_s = ah_s + 64 * SLD;
        for (int rr = 0; rr < 8; ++rr) {
            const int row = wid * 8 + rr;
            float v0 = sc[row][lane]      * 0.125f;
            float v1 = sc[row][lane + 32] * 0.125f;
            float m = fmaxf(v0, v1);
#pragma unroll
            for (int off = 16; off > 0; off >>= 1)
                m = fmaxf(m, __shfl_xor_sync(0xFFFFFFFFu, m, off));
            float e0 = __expf(v0 - m);
            float e1 = __expf(v1 - m);
            float sum = e0 + e1;
#pragma unroll
            for (int off = 16; off > 0; off >>= 1)
                sum += __shfl_xor_sync(0xFFFFFFFFu, sum, off);
            const float inv = 1.0f / sum;
            const float p0 = e0 * inv, p1 = e1 * inv;
            __half h0 = __float2half_rn(p0);
            __half h1 = __float2half_rn(p1);
            ah_s[row * SLD + lane]      = h0;
            ah_s[row * SLD + lane + 32] = h1;
            al_s[row * SLD + lane]      = __float2half_rn(p0 - __half2float(h0));
            al_s[row * SLD + lane + 32] = __float2half_rn(p1 - __half2float(h1));
        }
        __syncthreads();
    }

    // ================= phase 2: AV (64-row v chunks x16) =================
    {
        const uint32_t ah_a = dbase + ATT_OFF;
        const uint32_t al_a = ah_a + TILE64;

        const __half* vsrc[4];
        uint32_t      vdst[4];
#pragma unroll
        for (int j = 0; j < 4; ++j) {
            const int c2 = tid + j * 256;
            const int t  = c2 >> 9;                // 0=vh, 1=vl
            const int r  = (c2 >> 3) & 63;
            const int cc = c2 & 7;
            vsrc[j] = (t ? vl : vh) + bb64 + r * 64 + cc * 8;
            vdst[j] = (uint32_t)(t * TILE64) + (uint32_t)(r * SLD + cc * 8) * 2;
        }

        auto issue2 = [&](int c, int buf) {
            const uint32_t sb = dbase + (uint32_t)buf * (2 * TILE64);
            const size_t ofs = (size_t)c * 4096;
#pragma unroll
            for (int j = 0; j < 4; ++j)
                cp16(sb + vdst[j], vsrc[j] + ofs);
            cp_commit();
        };

        const int wm = (wid & 3) * 16;     // n strip
        const int wn = (wid >> 2) * 32;    // d strip
        const int arow = wm + (lt & 1) * 8 + lr;
        const int akg  = lt >> 1;
        const int brow = wn + (lt >> 1) * 8 + lr;
        const int bkg  = lt & 1;
        const int bbn = b >> 4;
        const int nh  = b & 15;

        issue2(0, 0);

        for (int c = 0; c < 16; ++c) {
            cp_wait<0>();
            __syncthreads();
            if (c + 1 < 16) issue2(c + 1, (c + 1) & 1);

            const uint32_t sb = dbase + (uint32_t)(c & 1) * (2 * TILE64);
            const uint32_t vh_t = sb, vl_t = sb + TILE64;

            float acc[4][4];
#pragma unroll
            for (int i = 0; i < 4; i++)
#pragma unroll
                for (int j = 0; j < 4; j++) acc[i][j] = 0.f;

#pragma unroll
            for (int s = 0; s < 4; ++s) {
                const uint32_t a_off =
                    (uint32_t)((arow * SLD + (s * 2 + akg) * 8) * 2);
                const uint32_t b_off0 =
                    (uint32_t)((brow * SLD + (s * 2 + bkg) * 8) * 2);
                const uint32_t b_off1 =
                    (uint32_t)(((brow + 16) * SLD + (s * 2 + bkg) * 8) * 2);
                uint32_t aH[4], aL[4], bHf[2][4], bLf[2][4];
                ldsm_x4(aH, vh_t + a_off);
                ldsm_x4(aL, vl_t + a_off);
                ldsm_x4(bHf[0], ah_a + b_off0);
                ldsm_x4(bHf[1], ah_a + b_off1);
                ldsm_x4(bLf[0], al_a + b_off0);
                ldsm_x4(bLf[1], al_a + b_off1);
#pragma unroll
                for (int ni = 0; ni < 4; ++ni)
                    mma16816(acc[ni], aH, &bHf[ni >> 1][(ni & 1) * 2]);
#pragma unroll
                for (int ni = 0; ni < 4; ++ni)
                    mma16816(acc[ni], aH, &bLf[ni >> 1][(ni & 1) * 2]);
#pragma unroll
                for (int ni = 0; ni < 4; ++ni)
                    mma16816(acc[ni], aL, &bHf[ni >> 1][(ni & 1) * 2]);
            }

            const int n0 = c * 64;
#pragma unroll
            for (int ni = 0; ni < 4; ++ni) {
                const int dcol = wn + ni * 8 + (lane & 3) * 2;
                const int nrow = n0 + wm + (lane >> 2);
#pragma unroll
                for (int h = 0; h < 2; ++h) {
                    const int n = nrow + h * 8;
                    const size_t idx = ((size_t)bbn * NN + n) * HH + nh * 64 + dcol;
                    *reinterpret_cast<__half2*>(&ch[idx]) =
                        __float22half2_rn(make_float2(acc[ni][h * 2],
                                                      acc[ni][h * 2 + 1]));
                }
            }
        }
    }
}

// ============================================================
// launch  (my call #4 = hgemm<3> k, profiled control)
// ============================================================
extern "C" void kernel_launch(void* const* d_in, const int* in_sizes, int n_in,
                              void* d_out, int out_size)
{
    const float* query  = (const float*)d_in[0];
    const float* key    = (const float*)d_in[1];
    const float* value  = (const float*)d_in[2];
    const float* key_pe = (const float*)d_in[3];
    const float* Wq     = (const float*)d_in[4];
    const float* Wk     = (const float*)d_in[5];
    const float* Wv     = (const float*)d_in[6];
    const float* Wo     = (const float*)d_in[7];
    float* out = (float*)d_out;

    __half *qh, *ql, *kh, *kl, *vh, *vl, *xh, *wh, *ch;
    cudaGetSymbolAddress((void**)&qh, g_qh);
    cudaGetSymbolAddress((void**)&ql, g_ql);
    cudaGetSymbolAddress((void**)&kh, g_kh);
    cudaGetSymbolAddress((void**)&kl, g_kl);
    cudaGetSymbolAddress((void**)&vh, g_vh);
    cudaGetSymbolAddress((void**)&vl, g_vl);
    cudaGetSymbolAddress((void**)&xh, g_xh);
    cudaGetSymbolAddress((void**)&wh, g_wh);
    cudaGetSymbolAddress((void**)&ch, g_ch);

    static bool attr_done = false;
    if (!attr_done) {
        cudaFuncSetAttribute(hgemm_nt<0>, cudaFuncAttributeMaxDynamicSharedMemorySize, GSMEM);
        cudaFuncSetAttribute(hgemm_nt<2>, cudaFuncAttributeMaxDynamicSharedMemorySize, GSMEM);
        cudaFuncSetAttribute(hgemm_nt<3>, cudaFuncAttributeMaxDynamicSharedMemorySize, GSMEM);
        cudaFuncSetAttribute(attn_fused, cudaFuncAttributeMaxDynamicSharedMemorySize, ATSM);
        attr_done = true;
    }

    const int nX = MROWS * HH;
    const int nW = HH * HH;

    dim3 gg(HH / BN, MROWS / BM);   // (4, 256)

    CvtSrc xs; xs.s[0] = query; xs.s[1] = key; xs.s[2] = value; xs.s[3] = nullptr;
    CvtSrc ws; ws.s[0] = Wq; ws.s[1] = Wk; ws.s[2] = Wv; ws.s[3] = Wo;

    cvt_multi<<<dim3(nX / 2048, 3), 256>>>(xs, xh, nX);                                 // 1
    cvt_multi<<<dim3(nW / 2048, 4), 256>>>(ws, wh, nW);                                 // 2

    hgemm_nt<2><<<gg, 512, GSMEM>>>(xh + 0 * (size_t)nX, wh + 0 * (size_t)nW,
                                    nullptr, qh, ql, nullptr);                          // 3
    hgemm_nt<3><<<gg, 512, GSMEM>>>(xh + 1 * (size_t)nX, wh + 1 * (size_t)nW,
                                    nullptr, kh, kl, key_pe);                           // 4 <- profiled
    hgemm_nt<2><<<gg, 512, GSMEM>>>(xh + 2 * (size_t)nX, wh + 2 * (size_t)nW,
                                    nullptr, vh, vl, nullptr);                          // 5

    attn_fused<<<BH, 256, ATSM>>>(qh, ql, kh, kl, vh, vl, ch);                          // 6

    hgemm_nt<0><<<gg, 512, GSMEM>>>(ch, wh + 3 * (size_t)nW, out, nullptr, nullptr,
                                    nullptr);                                           // 7
}

// round 17
// speedup vs baseline: 1.0209x; 1.0070x over previous
#include <cuda_runtime.h>
#include <cuda_fp16.h>
#include <cstdint>

#define BB   32
#define NN   1024
#define HH   1024
#define NHD  16
#define DD   64
#define BH   (BB*NHD)     // 512
#define MROWS (BB*NN)     // 32768

// -------- scratch (device globals) --------
__device__ __half g_qh[BH * NN * DD];        // q hi/lo fp16
__device__ __half g_ql[BH * NN * DD];
__device__ __half g_kh[BH * NN * DD];        // khat = k+pe hi/lo fp16
__device__ __half g_kl[BH * NN * DD];
__device__ __half g_vh[BH * NN * DD];        // v hi/lo fp16
__device__ __half g_vl[BH * NN * DD];
__device__ __half g_xh[3][MROWS * HH];       // fp16 inputs
__device__ __half g_wh[4][HH * HH];          // fp16 weights
__device__ __half g_ch[MROWS * HH];          // fp16 ctx

// ============================================================
// fp32 -> fp16 convert, multi-source
// ============================================================
struct alignas(16) H8 { __half2 a, b, c, d; };
struct CvtSrc { const float* s[4]; };

__global__ void cvt_multi(CvtSrc ps, __half* __restrict__ out, int n)
{
    const float* __restrict__ in = ps.s[blockIdx.y];
    __half* __restrict__ dst = out + (size_t)blockIdx.y * n;
    int idx = (blockIdx.x * blockDim.x + threadIdx.x) * 8;
    if (idx >= n) return;
    float4 a = *reinterpret_cast<const float4*>(in + idx);
    float4 b = *reinterpret_cast<const float4*>(in + idx + 4);
    H8 o;
    o.a = __floats2half2_rn(a.x, a.y);
    o.b = __floats2half2_rn(a.z, a.w);
    o.c = __floats2half2_rn(b.x, b.y);
    o.d = __floats2half2_rn(b.z, b.w);
    *reinterpret_cast<H8*>(dst + idx) = o;
}

// ============================================================
// mma.sync helpers
// ============================================================
__device__ __forceinline__ uint32_t smem_u32(const void* p) {
    return (uint32_t)__cvta_generic_to_shared(p);
}
__device__ __forceinline__ void cp16(uint32_t dst, const void* src) {
    asm volatile("cp.async.cg.shared.global [%0], [%1], 16;\n" :: "r"(dst), "l"(src));
}
__device__ __forceinline__ void cp_commit() {
    asm volatile("cp.async.commit_group;\n");
}
template<int N> __device__ __forceinline__ void cp_wait() {
    asm volatile("cp.async.wait_group %0;\n" :: "n"(N));
}
__device__ __forceinline__ void ldsm_x4(uint32_t* r, uint32_t addr) {
    asm volatile("ldmatrix.sync.aligned.m8n8.x4.shared.b16 {%0,%1,%2,%3}, [%4];\n"
                 : "=r"(r[0]), "=r"(r[1]), "=r"(r[2]), "=r"(r[3]) : "r"(addr));
}
__device__ __forceinline__ void ldsm_x4_t(uint32_t* r, uint32_t addr) {
    asm volatile("ldmatrix.sync.aligned.m8n8.x4.trans.shared.b16 {%0,%1,%2,%3}, [%4];\n"
                 : "=r"(r[0]), "=r"(r[1]), "=r"(r[2]), "=r"(r[3]) : "r"(addr));
}
__device__ __forceinline__ void mma16816(float* c, const uint32_t* a, const uint32_t* b) {
    asm volatile("mma.sync.aligned.m16n8k16.row.col.f32.f16.f16.f32 "
                 "{%0,%1,%2,%3}, {%4,%5,%6,%7}, {%8,%9}, {%0,%1,%2,%3};\n"
                 : "+f"(c[0]), "+f"(c[1]), "+f"(c[2]), "+f"(c[3])
                 : "r"(a[0]), "r"(a[1]), "r"(a[2]), "r"(a[3]),
                   "r"(b[0]), "r"(b[1]));
}
__device__ __forceinline__ void split2(float c0, float c1, __half2& H, __half2& L) {
    H = __float22half2_rn(make_float2(c0, c1));
    float2 hf = __half22float2(H);
    L = __float22half2_rn(make_float2(c0 - hf.x, c1 - hf.y));
}

// ============================================================
// HMMA GEMM NT: C[m,h] = sum_k A[m,k]*W[h,k]  (fp16 in, fp32 acc)
// CTA 128x256, 512 threads, warp 32x64, K-tile 128, 2 stages.
// MODE 0: fp32 row-major, smem-staged coalesced stores
// MODE 2: hi/lo head-split, smem-staged   MODE 3: MODE2 + pe
// ============================================================
#define BM 128
#define BN 256
#define BKH 128
#define LDSS 136
#define NITER (HH / BKH)                  // 8
#define STG_A (BM * LDSS * 2)             // 34816 B
#define STG_B (BN * LDSS * 2)             // 69632 B
#define STG   (STG_A + STG_B)             // 104448 B
#define GSMEM (2 * STG)                   // 208896 B

template<int MODE>
__global__ void __launch_bounds__(512, 1)
hgemm_nt(const __half* __restrict__ A, const __half* __restrict__ W,
         float* __restrict__ C, __half* __restrict__ Ch, __half* __restrict__ Cl,
         const float* __restrict__ PE)
{
    extern __shared__ __align__(16) char dynsm[];
    const uint32_t dbase = smem_u32(dynsm);

    const int tid  = threadIdx.x;
    const int lane = tid & 31;
    const int wid  = tid >> 5;
    const int bm = blockIdx.y * BM;
    const int bn = blockIdx.x * BN;

    const __half* gsrc[12];
    uint32_t      soff[12];
#pragma unroll
    for (int i = 0; i < 12; ++i) {
        const int chunk = tid + i * 512;
        const int row = chunk >> 4;
        const int c   = chunk & 15;
        if (row < BM) {
            gsrc[i] = A + (size_t)(bm + row) * HH + c * 8;
            soff[i] = (uint32_t)(row * LDSS + c * 8) * 2;
        } else {
            const int r2 = row - BM;
            gsrc[i] = W + (size_t)(bn + r2) * HH + c * 8;
            soff[i] = (uint32_t)STG_A + (uint32_t)(r2 * LDSS + c * 8) * 2;
        }
    }

    auto issue = [&](int it, int buf) {
        const uint32_t sb = dbase + (uint32_t)buf * STG;
        const size_t kofs = (size_t)it * BKH;
#pragma unroll
        for (int i = 0; i < 12; ++i)
            cp16(sb + soff[i], gsrc[i] + kofs);
        cp_commit();
    };

    const int wm = (wid & 3) * 32;
    const int wn = (wid >> 2) * 64;
    const int lr = lane & 7;
    const int lt = lane >> 3;
    const int arow_f = wm + (lt & 1) * 8 + lr;
    const int akg    = lt >> 1;
    const int brow_f = wn + (lt >> 1) * 8 + lr;
    const int bkg    = lt & 1;

    float acc[2][8][4];
#pragma unroll
    for (int i = 0; i < 2; i++)
#pragma unroll
        for (int j = 0; j < 8; j++)
#pragma unroll
            for (int r = 0; r < 4; r++) acc[i][j][r] = 0.f;

    issue(0, 0);

    for (int it = 0; it < NITER; ++it) {
        cp_wait<0>();
        __syncthreads();
        if (it + 1 < NITER) issue(it + 1, (it + 1) & 1);
        const uint32_t sb = dbase + (uint32_t)(it & 1) * STG;

#pragma unroll
        for (int s = 0; s < 8; ++s) {
            uint32_t af[2][4];
#pragma unroll
            for (int mi = 0; mi < 2; ++mi)
                ldsm_x4(af[mi], sb +
                    (uint32_t)(((arow_f + mi * 16) * LDSS + (s * 2 + akg) * 8) * 2));
            uint32_t bf[4][4];
#pragma unroll
            for (int p = 0; p < 4; ++p)
                ldsm_x4(bf[p], sb + STG_A +
                    (uint32_t)(((brow_f + p * 16) * LDSS + (s * 2 + bkg) * 8) * 2));
#pragma unroll
            for (int mi = 0; mi < 2; ++mi)
#pragma unroll
                for (int ni = 0; ni < 8; ++ni)
                    mma16816(acc[mi][ni], af[mi], &bf[ni >> 1][(ni & 1) * 2]);
        }
    }

    if (MODE == 0) {
        // ---- smem-staged fp32 epilogue: 128 x 256 tile, row stride 268 ----
        __syncthreads();
        float* sc = reinterpret_cast<float*>(dynsm);
#pragma unroll
        for (int mi = 0; mi < 2; ++mi) {
#pragma unroll
            for (int ni = 0; ni < 8; ++ni) {
                const int n0 = wn + ni * 8 + (lane & 3) * 2;
#pragma unroll
                for (int h = 0; h < 2; ++h) {
                    const int ml = wm + mi * 16 + (lane >> 2) + h * 8;
                    *reinterpret_cast<float2*>(&sc[ml * 268 + n0]) =
                        make_float2(acc[mi][ni][h * 2 + 0], acc[mi][ni][h * 2 + 1]);
                }
            }
        }
        __syncthreads();
        // coalesced writeback: 8192 16B chunks, 16 per thread
#pragma unroll
        for (int i = 0; i < 16; ++i) {
            const int c = tid + i * 512;
            const int r = c >> 6, seg = c & 63;
            const int m = bm + r;
            *reinterpret_cast<float4*>(&C[(size_t)m * HH + bn + seg * 4]) =
                *reinterpret_cast<float4*>(&sc[r * 268 + seg * 4]);
        }
    } else {
        __syncthreads();

        float* pes = reinterpret_cast<float*>(dynsm);
        if (MODE == 3) {
            const float* pesrc = PE + (size_t)(bm & 1023) * 64;
#pragma unroll
            for (int i = tid; i < 2048; i += 512) {
                const int r  = i >> 4;
                const int c4 = (i & 15) * 4;
                *reinterpret_cast<float4*>(&pes[r * 68 + c4]) =
                    *reinterpret_cast<const float4*>(&pesrc[r * 64 + c4]);
            }
            __syncthreads();
        }

        __half* s_hi = reinterpret_cast<__half*>(dynsm + (MODE == 3 ? 34816 : 0));
        __half* s_lo = s_hi + 512 * 72;
        const int nh_l = wid >> 2;

#pragma unroll
        for (int mi = 0; mi < 2; ++mi) {
#pragma unroll
            for (int ni = 0; ni < 8; ++ni) {
                const int d = ni * 8 + (lane & 3) * 2;
#pragma unroll
                for (int h = 0; h < 2; ++h) {
                    const int ml = wm + mi * 16 + (lane >> 2) + h * 8;
                    float c0 = acc[mi][ni][h * 2 + 0];
                    float c1 = acc[mi][ni][h * 2 + 1];
                    if (MODE == 3) {
                        c0 += pes[ml * 68 + d];
                        c1 += pes[ml * 68 + d + 1];
                    }
                    __half2 H, L;
                    split2(c0, c1, H, L);
                    const int r = nh_l * 128 + ml;
                    *reinterpret_cast<__half2*>(&s_hi[r * 72 + d]) = H;
                    *reinterpret_cast<__half2*>(&s_lo[r * 72 + d]) = L;
                }
            }
        }
        __syncthreads();

        const int nh_base = bn >> 6;
#pragma unroll
        for (int i = 0; i < 8; ++i) {
            const int c = tid + i * 512;
            const int r = c >> 3, seg = c & 7;
            const int ml = r & 127, nhl2 = r >> 7;
            const int m = bm + ml;
            const int bI = m >> 10, n = m & 1023;
            const size_t dst = ((size_t)(bI * NHD + nh_base + nhl2) * NN + n) * DD + seg * 8;
            *reinterpret_cast<uint4*>(&Ch[dst]) =
                *reinterpret_cast<uint4*>(&s_hi[r * 72 + seg * 8]);
            *reinterpret_cast<uint4*>(&Cl[dst]) =
                *reinterpret_cast<uint4*>(&s_lo[r * 72 + seg * 8]);
        }
    }
}

// ============================================================
// attn_fused (R14/R15 config): per b — scores+softmax+AV.
// Phase 1: 64-row chunks x16, fragment-shared 3-term hi/lo MMA.
// smem 92160 B, occ 2.
// ============================================================
#define SLD 72                         // tile stride, halfs
#define TILE (64 * SLD * 2)            // 9216 B per tile
#define S1STG (4 * TILE)               // 36864 B per phase-1 stage
#define ATT_OFF (2 * S1STG)            // 73728: attn hi tile
#define ATSM (ATT_OFF + 2 * TILE)      // 92160 total

__global__ void __launch_bounds__(256, 2)
attn_fused(const __half* __restrict__ qh, const __half* __restrict__ ql,
           const __half* __restrict__ kh, const __half* __restrict__ kl,
           const __half* __restrict__ vh, const __half* __restrict__ vl,
           __half* __restrict__ ch)
{
    const int b = blockIdx.x;
    extern __shared__ __align__(16) char dynsm[];
    const uint32_t dbase = smem_u32(dynsm);

    const int tid = threadIdx.x;
    const int lane = tid & 31;
    const int wid = tid >> 5;
    const size_t bb64 = (size_t)b * (NN * DD);
    const int lr = lane & 7;
    const int lt = lane >> 3;

    // ================= phase 1: scores =================
    {
        const __half* bases[4] = { qh + bb64, ql + bb64, kh + bb64, kl + bb64 };
        const __half* lsrc[8];
        uint32_t      ldst[8];
#pragma unroll
        for (int j = 0; j < 8; ++j) {
            const int c2 = tid + j * 256;
            const int t  = c2 >> 9;
            const int r  = (c2 >> 3) & 63;
            const int cc = c2 & 7;
            lsrc[j] = bases[t] + r * 64 + cc * 8;
            ldst[j] = (uint32_t)(t * TILE) + (uint32_t)(r * SLD + cc * 8) * 2;
        }

        auto issue1 = [&](int c, int buf) {
            const uint32_t sb = dbase + (uint32_t)buf * S1STG;
            const size_t ofs = (size_t)c * 4096;
#pragma unroll
            for (int j = 0; j < 8; ++j)
                cp16(sb + ldst[j], lsrc[j] + ofs);
            cp_commit();
        };

        const int wm = (wid & 3) * 16;      // d strip
        const int wn = (wid >> 2) * 32;     // e strip
        const int a_moff = (lt & 1) * 8;
        const int a_koff = (lt >> 1) * 8;
        const int b_koff = (lt & 1) * 8;
        const int b_noff = (lt >> 1) * 8;

        float acc[4][4];
#pragma unroll
        for (int i = 0; i < 4; i++)
#pragma unroll
            for (int j = 0; j < 4; j++) acc[i][j] = 0.f;

        issue1(0, 0);

        for (int c = 0; c < 16; ++c) {
            cp_wait<0>();
            __syncthreads();
            if (c + 1 < 16) issue1(c + 1, (c + 1) & 1);

            const uint32_t sb = dbase + (uint32_t)(c & 1) * S1STG;
            const uint32_t qh_t = sb,          ql_t = sb + TILE;
            const uint32_t kh_t = sb + 2*TILE, kl_t = sb + 3*TILE;
#pragma unroll
            for (int s = 0; s < 4; ++s) {
                const uint32_t a_off =
                    (uint32_t)(((s * 16 + a_koff + lr) * SLD + wm + a_moff) * 2);
                const uint32_t b_off0 =
                    (uint32_t)(((s * 16 + b_koff + lr) * SLD + wn + b_noff) * 2);
                const uint32_t b_off1 =
                    (uint32_t)(((s * 16 + b_koff + lr) * SLD + wn + 16 + b_noff) * 2);
                uint32_t aH[4], aL[4], bHf[2][4], bLf[2][4];
                ldsm_x4_t(aH, qh_t + a_off);
                ldsm_x4_t(aL, ql_t + a_off);
                ldsm_x4_t(bHf[0], kh_t + b_off0);
                ldsm_x4_t(bHf[1], kh_t + b_off1);
                ldsm_x4_t(bLf[0], kl_t + b_off0);
                ldsm_x4_t(bLf[1], kl_t + b_off1);
#pragma unroll
                for (int ni = 0; ni < 4; ++ni)
                    mma16816(acc[ni], aH, &bHf[ni >> 1][(ni & 1) * 2]);
#pragma unroll
                for (int ni = 0; ni < 4; ++ni)
                    mma16816(acc[ni], aH, &bLf[ni >> 1][(ni & 1) * 2]);
#pragma unroll
                for (int ni = 0; ni < 4; ++ni)
                    mma16816(acc[ni], aL, &bHf[ni >> 1][(ni & 1) * 2]);
            }
        }

        __syncthreads();
        float (*sc)[68] = reinterpret_cast<float(*)[68]>(dynsm);
#pragma unroll
        for (int ni = 0; ni < 4; ++ni) {
            const int e = wn + ni * 8 + (lane & 3) * 2;
            const int r = wm + (lane >> 2);
            sc[r][e]         = acc[ni][0];
            sc[r][e + 1]     = acc[ni][1];
            sc[r + 8][e]     = acc[ni][2];
            sc[r + 8][e + 1] = acc[ni][3];
        }
        __syncthreads();

        __half* ah_s = reinterpret_cast<__half*>(dynsm + ATT_OFF);
        __half* al_s = ah_s + 64 * SLD;
        for (int rr = 0; rr < 8; ++rr) {
            const int row = wid * 8 + rr;
            float v0 = sc[row][lane]      * 0.125f;
            float v1 = sc[row][lane + 32] * 0.125f;
            float m = fmaxf(v0, v1);
#pragma unroll
            for (int off = 16; off > 0; off >>= 1)
                m = fmaxf(m, __shfl_xor_sync(0xFFFFFFFFu, m, off));
            float e0 = __expf(v0 - m);
            float e1 = __expf(v1 - m);
            float sum = e0 + e1;
#pragma unroll
            for (int off = 16; off > 0; off >>= 1)
                sum += __shfl_xor_sync(0xFFFFFFFFu, sum, off);
            const float inv = 1.0f / sum;
            const float p0 = e0 * inv, p1 = e1 * inv;
            __half h0 = __float2half_rn(p0);
            __half h1 = __float2half_rn(p1);
            ah_s[row * SLD + lane]      = h0;
            ah_s[row * SLD + lane + 32] = h1;
            al_s[row * SLD + lane]      = __float2half_rn(p0 - __half2float(h0));
            al_s[row * SLD + lane + 32] = __float2half_rn(p1 - __half2float(h1));
        }
        __syncthreads();
    }

    // ================= phase 2: AV =================
    {
        const uint32_t ah_a = dbase + ATT_OFF;
        const uint32_t al_a = ah_a + TILE;

        const __half* vsrc[4];
        uint32_t      vdst[4];
#pragma unroll
        for (int j = 0; j < 4; ++j) {
            const int c2 = tid + j * 256;
            const int t  = c2 >> 9;
            const int r  = (c2 >> 3) & 63;
            const int cc = c2 & 7;
            vsrc[j] = (t ? vl : vh) + bb64 + r * 64 + cc * 8;
            vdst[j] = (uint32_t)(t * TILE) + (uint32_t)(r * SLD + cc * 8) * 2;
        }

        auto issue2 = [&](int c, int buf) {
            const uint32_t sb = dbase + (uint32_t)buf * (2 * TILE);
            const size_t ofs = (size_t)c * 4096;
#pragma unroll
            for (int j = 0; j < 4; ++j)
                cp16(sb + vdst[j], vsrc[j] + ofs);
            cp_commit();
        };

        const int wm = (wid & 3) * 16;     // n strip
        const int wn = (wid >> 2) * 32;    // d strip
        const int arow = wm + (lt & 1) * 8 + lr;
        const int akg  = lt >> 1;
        const int brow = wn + (lt >> 1) * 8 + lr;
        const int bkg  = lt & 1;
        const int bbn = b >> 4;
        const int nh  = b & 15;

        issue2(0, 0);

        for (int c = 0; c < 16; ++c) {
            cp_wait<0>();
            __syncthreads();
            if (c + 1 < 16) issue2(c + 1, (c + 1) & 1);

            const uint32_t sb = dbase + (uint32_t)(c & 1) * (2 * TILE);
            const uint32_t vh_t = sb, vl_t = sb + TILE;

            float acc[4][4];
#pragma unroll
            for (int i = 0; i < 4; i++)
#pragma unroll
                for (int j = 0; j < 4; j++) acc[i][j] = 0.f;

#pragma unroll
            for (int s = 0; s < 4; ++s) {
                const uint32_t a_off =
                    (uint32_t)((arow * SLD + (s * 2 + akg) * 8) * 2);
                const uint32_t b_off0 =
                    (uint32_t)((brow * SLD + (s * 2 + bkg) * 8) * 2);
                const uint32_t b_off1 =
                    (uint32_t)(((brow + 16) * SLD + (s * 2 + bkg) * 8) * 2);
                uint32_t aH[4], aL[4], bHf[2][4], bLf[2][4];
                ldsm_x4(aH, vh_t + a_off);
                ldsm_x4(aL, vl_t + a_off);
                ldsm_x4(bHf[0], ah_a + b_off0);
                ldsm_x4(bHf[1], ah_a + b_off1);
                ldsm_x4(bLf[0], al_a + b_off0);
                ldsm_x4(bLf[1], al_a + b_off1);
#pragma unroll
                for (int ni = 0; ni < 4; ++ni)
                    mma16816(acc[ni], aH, &bHf[ni >> 1][(ni & 1) * 2]);
#pragma unroll
                for (int ni = 0; ni < 4; ++ni)
                    mma16816(acc[ni], aH, &bLf[ni >> 1][(ni & 1) * 2]);
#pragma unroll
                for (int ni = 0; ni < 4; ++ni)
                    mma16816(acc[ni], aL, &bHf[ni >> 1][(ni & 1) * 2]);
            }

            const int n0 = c * 64;
#pragma unroll
            for (int ni = 0; ni < 4; ++ni) {
                const int dcol = wn + ni * 8 + (lane & 3) * 2;
                const int nrow = n0 + wm + (lane >> 2);
#pragma unroll
                for (int h = 0; h < 2; ++h) {
                    const int n = nrow + h * 8;
                    const size_t idx = ((size_t)bbn * NN + n) * HH + nh * 64 + dcol;
                    *reinterpret_cast<__half2*>(&ch[idx]) =
                        __float22half2_rn(make_float2(acc[ni][h * 2],
                                                      acc[ni][h * 2 + 1]));
                }
            }
        }
    }
}

// ============================================================
// launch  (my call #4 = hgemm<3> k, profiled control)
// ============================================================
extern "C" void kernel_launch(void* const* d_in, const int* in_sizes, int n_in,
                              void* d_out, int out_size)
{
    const float* query  = (const float*)d_in[0];
    const float* key    = (const float*)d_in[1];
    const float* value  = (const float*)d_in[2];
    const float* key_pe = (const float*)d_in[3];
    const float* Wq     = (const float*)d_in[4];
    const float* Wk     = (const float*)d_in[5];
    const float* Wv     = (const float*)d_in[6];
    const float* Wo     = (const float*)d_in[7];
    float* out = (float*)d_out;

    __half *qh, *ql, *kh, *kl, *vh, *vl, *xh, *wh, *ch;
    cudaGetSymbolAddress((void**)&qh, g_qh);
    cudaGetSymbolAddress((void**)&ql, g_ql);
    cudaGetSymbolAddress((void**)&kh, g_kh);
    cudaGetSymbolAddress((void**)&kl, g_kl);
    cudaGetSymbolAddress((void**)&vh, g_vh);
    cudaGetSymbolAddress((void**)&vl, g_vl);
    cudaGetSymbolAddress((void**)&xh, g_xh);
    cudaGetSymbolAddress((void**)&wh, g_wh);
    cudaGetSymbolAddress((void**)&ch, g_ch);

    static bool attr_done = false;
    if (!attr_done) {
        cudaFuncSetAttribute(hgemm_nt<0>, cudaFuncAttributeMaxDynamicSharedMemorySize, GSMEM);
        cudaFuncSetAttribute(hgemm_nt<2>, cudaFuncAttributeMaxDynamicSharedMemorySize, GSMEM);
        cudaFuncSetAttribute(hgemm_nt<3>, cudaFuncAttributeMaxDynamicSharedMemorySize, GSMEM);
        cudaFuncSetAttribute(attn_fused, cudaFuncAttributeMaxDynamicSharedMemorySize, ATSM);
        attr_done = true;
    }

    const int nX = MROWS * HH;
    const int nW = HH * HH;

    dim3 gg(HH / BN, MROWS / BM);   // (4, 256)

    CvtSrc xs; xs.s[0] = query; xs.s[1] = key; xs.s[2] = value; xs.s[3] = nullptr;
    CvtSrc ws; ws.s[0] = Wq; ws.s[1] = Wk; ws.s[2] = Wv; ws.s[3] = Wo;

    cvt_multi<<<dim3(nX / 2048, 3), 256>>>(xs, xh, nX);                                 // 1
    cvt_multi<<<dim3(nW / 2048, 4), 256>>>(ws, wh, nW);                                 // 2

    hgemm_nt<2><<<gg, 512, GSMEM>>>(xh + 0 * (size_t)nX, wh + 0 * (size_t)nW,
                                    nullptr, qh, ql, nullptr);                          // 3
    hgemm_nt<3><<<gg, 512, GSMEM>>>(xh + 1 * (size_t)nX, wh + 1 * (size_t)nW,
                                    nullptr, kh, kl, key_pe);                           // 4 <- profiled
    hgemm_nt<2><<<gg, 512, GSMEM>>>(xh + 2 * (size_t)nX, wh + 2 * (size_t)nW,
                                    nullptr, vh, vl, nullptr);                          // 5

    attn_fused<<<BH, 256, ATSM>>>(qh, ql, kh, kl, vh, vl, ch);                          // 6

    hgemm_nt<0><<<gg, 512, GSMEM>>>(ch, wh + 3 * (size_t)nW, out, nullptr, nullptr,
                                    nullptr);                                           // 7
}